// round 1
// baseline (speedup 1.0000x reference)
#include <cuda_runtime.h>
#include <cstddef>

#define NB 32
#define LQ 64
#define LV 128
#define QS 512
#define FS 1024
#define BN 512

// Scratch (device globals — no allocation)
__device__ float g_Wh[(size_t)NB * LQ * BN];   // Wh + bias, [b*LQ+q][n]
__device__ float g_Uv[(size_t)NB * LV * BN];   // Uv,        [b*LV+v][n]

// Accurate-enough fast tanh: 2 MUFU (EX2 + RCP) + ~4 FMA, rel err ~1e-6
__device__ __forceinline__ float fast_tanh(float x) {
    float e = __expf(2.0f * x);
    return 1.0f - __fdividef(2.0f, e + 1.0f);
}

// ---------------------------------------------------------------------------
// NT GEMM: C[M,N] = A[M,K] * B[N,K]^T (+ bias[n]).  64x64 tile, K-chunk 16,
// 256 threads, 4x4 register blocking.
// ---------------------------------------------------------------------------
__global__ __launch_bounds__(256) void gemm_nt_kernel(
    const float* __restrict__ A, const float* __restrict__ Bm,
    const float* __restrict__ bias, float* __restrict__ C,
    int M, int N, int K)
{
    __shared__ float As[16][65];
    __shared__ float Bs[16][65];
    const int tid = threadIdx.x;
    const int tx = tid & 15, ty = tid >> 4;
    const int m0 = blockIdx.y * 64, n0 = blockIdx.x * 64;
    const int lrow = tid >> 2;          // 0..63
    const int lk = (tid & 3) * 4;       // 0,4,8,12

    float acc[4][4];
#pragma unroll
    for (int i = 0; i < 4; i++)
#pragma unroll
        for (int j = 0; j < 4; j++) acc[i][j] = 0.0f;

    for (int k0 = 0; k0 < K; k0 += 16) {
        float4 va = *reinterpret_cast<const float4*>(A + (size_t)(m0 + lrow) * K + k0 + lk);
        float4 vb = *reinterpret_cast<const float4*>(Bm + (size_t)(n0 + lrow) * K + k0 + lk);
        As[lk + 0][lrow] = va.x; As[lk + 1][lrow] = va.y;
        As[lk + 2][lrow] = va.z; As[lk + 3][lrow] = va.w;
        Bs[lk + 0][lrow] = vb.x; Bs[lk + 1][lrow] = vb.y;
        Bs[lk + 2][lrow] = vb.z; Bs[lk + 3][lrow] = vb.w;
        __syncthreads();
#pragma unroll
        for (int kk = 0; kk < 16; kk++) {
            float a[4], bb[4];
#pragma unroll
            for (int i = 0; i < 4; i++) a[i] = As[kk][ty + 16 * i];
#pragma unroll
            for (int j = 0; j < 4; j++) bb[j] = Bs[kk][tx + 16 * j];
#pragma unroll
            for (int i = 0; i < 4; i++)
#pragma unroll
                for (int j = 0; j < 4; j++)
                    acc[i][j] += a[i] * bb[j];
        }
        __syncthreads();
    }
#pragma unroll
    for (int i = 0; i < 4; i++) {
        int m = m0 + ty + 16 * i;
#pragma unroll
        for (int j = 0; j < 4; j++) {
            int n = n0 + tx + 16 * j;
            float v = acc[i][j];
            if (bias) v += bias[n];
            C[(size_t)m * N + n] = v;
        }
    }
}

// ---------------------------------------------------------------------------
// Energies: E[b,q,v] = sum_n w[n] * tanh(Wh[b,q,n] + Uv[b,v,n])  (bias folded
// into Wh). Block tile: 32 q x 64 v, n-chunk 16, 256 threads, 2x4 per thread.
// Designed MUFU-bound.
// ---------------------------------------------------------------------------
__global__ __launch_bounds__(256) void energy_kernel(
    const float* __restrict__ Wh, const float* __restrict__ Uv,
    const float* __restrict__ w, float* __restrict__ energies)
{
    __shared__ float As[16][33];   // [kk][q]
    __shared__ float Cs[16][65];   // [kk][v]
    __shared__ float ws[16];

    const int b = blockIdx.z;
    const int q0 = blockIdx.y * 32;
    const int v0 = blockIdx.x * 64;
    const int tid = threadIdx.x;
    const int tx = tid & 15, ty = tid >> 4;

    const float* Ab = Wh + ((size_t)b * LQ + q0) * BN;
    const float* Cb = Uv + ((size_t)b * LV + v0) * BN;

    float acc[2][4];
#pragma unroll
    for (int i = 0; i < 2; i++)
#pragma unroll
        for (int j = 0; j < 4; j++) acc[i][j] = 0.0f;

    for (int k0 = 0; k0 < BN; k0 += 16) {
#pragma unroll
        for (int e = 0; e < 2; e++) {           // 32q x 16k = 512 elems
            int id = tid + e * 256;
            int q = id >> 4, kk = id & 15;
            As[kk][q] = Ab[(size_t)q * BN + k0 + kk];
        }
#pragma unroll
        for (int e = 0; e < 4; e++) {           // 64v x 16k = 1024 elems
            int id = tid + e * 256;
            int v = id >> 4, kk = id & 15;
            Cs[kk][v] = Cb[(size_t)v * BN + k0 + kk];
        }
        if (tid < 16) ws[tid] = w[k0 + tid];
        __syncthreads();
#pragma unroll
        for (int kk = 0; kk < 16; kk++) {
            float wn = ws[kk];
            float a0 = As[kk][ty];
            float a1 = As[kk][ty + 16];
            float c[4];
#pragma unroll
            for (int j = 0; j < 4; j++) c[j] = Cs[kk][tx + 16 * j];
#pragma unroll
            for (int j = 0; j < 4; j++) {
                acc[0][j] += wn * fast_tanh(a0 + c[j]);
                acc[1][j] += wn * fast_tanh(a1 + c[j]);
            }
        }
        __syncthreads();
    }
#pragma unroll
    for (int i = 0; i < 2; i++) {
        int q = q0 + ty + 16 * i;
#pragma unroll
        for (int j = 0; j < 4; j++) {
            int v = v0 + tx + 16 * j;
            energies[((size_t)b * LQ + q) * LV + v] = acc[i][j];
        }
    }
}

// ---------------------------------------------------------------------------
// Softmax over v=128, one warp per (b,q) row.
// ---------------------------------------------------------------------------
__global__ __launch_bounds__(256) void softmax_kernel(
    const float* __restrict__ energies, float* __restrict__ weights)
{
    const int warps_per_blk = blockDim.x >> 5;
    const int row = blockIdx.x * warps_per_blk + (threadIdx.x >> 5);
    const int lane = threadIdx.x & 31;
    if (row >= NB * LQ) return;
    const float* e = energies + (size_t)row * LV;

    float v[4];
    float mx = -1e30f;
#pragma unroll
    for (int j = 0; j < 4; j++) { v[j] = e[lane + 32 * j]; mx = fmaxf(mx, v[j]); }
#pragma unroll
    for (int o = 16; o > 0; o >>= 1) mx = fmaxf(mx, __shfl_xor_sync(0xFFFFFFFFu, mx, o));
    float s = 0.0f;
#pragma unroll
    for (int j = 0; j < 4; j++) { v[j] = __expf(v[j] - mx); s += v[j]; }
#pragma unroll
    for (int o = 16; o > 0; o >>= 1) s += __shfl_xor_sync(0xFFFFFFFFu, s, o);
    float inv = __fdividef(1.0f, s);
#pragma unroll
    for (int j = 0; j < 4; j++) weights[(size_t)row * LV + lane + 32 * j] = v[j] * inv;
}

// ---------------------------------------------------------------------------
// aligned[b,q,f] = sum_v weights[b,q,v] * vis[b,v,f]; written into the
// concat output at column offset QS. Per-block: all 64 q x 64 f, K=128.
// ---------------------------------------------------------------------------
__global__ __launch_bounds__(256) void aligned_kernel(
    const float* __restrict__ weights, const float* __restrict__ vis,
    float* __restrict__ out_sem)
{
    __shared__ float Ws[LQ][LV];     // 64x128 = 32 KB
    __shared__ float Vs[16][64];     // 4 KB
    const int b = blockIdx.y;
    const int f0 = blockIdx.x * 64;
    const int tid = threadIdx.x;
    const int tx = tid & 15, ty = tid >> 4;

#pragma unroll
    for (int e = 0; e < 32; e++) {   // 8192 weights
        int id = tid + e * 256;
        Ws[id >> 7][id & 127] = weights[(size_t)b * LQ * LV + id];
    }

    float acc[4][4];
#pragma unroll
    for (int i = 0; i < 4; i++)
#pragma unroll
        for (int j = 0; j < 4; j++) acc[i][j] = 0.0f;

    for (int k0 = 0; k0 < LV; k0 += 16) {
        __syncthreads();
#pragma unroll
        for (int e = 0; e < 4; e++) {   // 16v x 64f
            int id = tid + e * 256;
            int kk = id >> 6, f = id & 63;
            Vs[kk][f] = vis[((size_t)b * LV + k0 + kk) * FS + f0 + f];
        }
        __syncthreads();
#pragma unroll
        for (int kk = 0; kk < 16; kk++) {
            float wv[4], vv[4];
#pragma unroll
            for (int i = 0; i < 4; i++) wv[i] = Ws[ty + 16 * i][k0 + kk];
#pragma unroll
            for (int j = 0; j < 4; j++) vv[j] = Vs[kk][tx + 16 * j];
#pragma unroll
            for (int i = 0; i < 4; i++)
#pragma unroll
                for (int j = 0; j < 4; j++)
                    acc[i][j] += wv[i] * vv[j];
        }
    }
#pragma unroll
    for (int i = 0; i < 4; i++) {
        int q = ty + 16 * i;
#pragma unroll
        for (int j = 0; j < 4; j++) {
            int f = f0 + tx + 16 * j;
            out_sem[((size_t)b * LQ + q) * (QS + FS) + QS + f] = acc[i][j];
        }
    }
}

// Copy phr_feats into concat output columns [0, QS)
__global__ __launch_bounds__(256) void copy_phr_kernel(
    const float* __restrict__ phr, float* __restrict__ out_sem)
{
    const size_t total4 = (size_t)NB * LQ * QS / 4;
    for (size_t i = (size_t)blockIdx.x * blockDim.x + threadIdx.x; i < total4;
         i += (size_t)gridDim.x * blockDim.x) {
        size_t elem = i * 4;
        size_t row = elem >> 9;       // /512
        size_t c = elem & 511;
        float4 v = *reinterpret_cast<const float4*>(phr + elem);
        *reinterpret_cast<float4*>(out_sem + row * (QS + FS) + c) = v;
    }
}

extern "C" void kernel_launch(void* const* d_in, const int* in_sizes, int n_in,
                              void* d_out, int out_size)
{
    const float* phr  = (const float*)d_in[0];  // [32,64,512]
    const float* vis  = (const float*)d_in[1];  // [32,128,1024]
    const float* W    = (const float*)d_in[2];  // [512,512]
    const float* U    = (const float*)d_in[3];  // [512,1024]
    const float* bias = (const float*)d_in[4];  // [512]
    const float* w    = (const float*)d_in[5];  // [1,512]

    float* out = (float*)d_out;
    float* out_sem = out;                                        // 32*64*1536
    float* out_w   = out + (size_t)NB * LQ * (QS + FS);          // 32*64*128
    float* out_e   = out_w + (size_t)NB * LQ * LV;               // 32*64*128

    float* Wh = nullptr;
    float* Uv = nullptr;
    cudaGetSymbolAddress((void**)&Wh, g_Wh);
    cudaGetSymbolAddress((void**)&Uv, g_Uv);

    // Wh = phr @ W^T + b    (M=2048, N=512, K=512)
    gemm_nt_kernel<<<dim3(BN / 64, (NB * LQ) / 64), 256>>>(phr, W, bias, Wh,
                                                           NB * LQ, BN, QS);
    // Uv = vis @ U^T        (M=4096, N=512, K=1024)
    gemm_nt_kernel<<<dim3(BN / 64, (NB * LV) / 64), 256>>>(vis, U, nullptr, Uv,
                                                           NB * LV, BN, FS);
    // energies
    energy_kernel<<<dim3(LV / 64, LQ / 32, NB), 256>>>(Wh, Uv, w, out_e);
    // softmax over v
    softmax_kernel<<<(NB * LQ) / 8, 256>>>(out_e, out_w);
    // aligned + concat
    aligned_kernel<<<dim3(FS / 64, NB), 256>>>(out_w, vis, out_sem);
    copy_phr_kernel<<<1024, 256>>>(phr, out_sem);
}

// round 2
// speedup vs baseline: 1.8943x; 1.8943x over previous
#include <cuda_runtime.h>
#include <cuda_bf16.h>
#include <cstdint>
#include <cstddef>

#define NB 32
#define LQ 64
#define LV 128
#define QS 512
#define FS 1024
#define BN 512

// Scratch (device globals — no allocation)
__device__ float g_Wh[(size_t)NB * LQ * BN];   // Wh + bias, [b*LQ+q][n]
__device__ float g_Uv[(size_t)NB * LV * BN];   // Uv,        [b*LV+v][n]

// ---------------------------------------------------------------------------
// Helpers
// ---------------------------------------------------------------------------
__device__ __forceinline__ uint32_t smem_u32(const void* p) {
    return (uint32_t)__cvta_generic_to_shared(p);
}

__device__ __forceinline__ void ldsm_x4(uint32_t& r0, uint32_t& r1,
                                        uint32_t& r2, uint32_t& r3, uint32_t addr) {
    asm volatile("ldmatrix.sync.aligned.m8n8.x4.shared.b16 {%0,%1,%2,%3}, [%4];"
                 : "=r"(r0), "=r"(r1), "=r"(r2), "=r"(r3) : "r"(addr));
}

__device__ __forceinline__ void ldsm_x2(uint32_t& r0, uint32_t& r1, uint32_t addr) {
    asm volatile("ldmatrix.sync.aligned.m8n8.x2.shared.b16 {%0,%1}, [%2];"
                 : "=r"(r0), "=r"(r1) : "r"(addr));
}

__device__ __forceinline__ void mma_bf16(float* d, const uint32_t* a, const uint32_t* b) {
    asm volatile(
        "mma.sync.aligned.m16n8k16.row.col.f32.bf16.bf16.f32 "
        "{%0,%1,%2,%3}, {%4,%5,%6,%7}, {%8,%9}, {%0,%1,%2,%3};"
        : "+f"(d[0]), "+f"(d[1]), "+f"(d[2]), "+f"(d[3])
        : "r"(a[0]), "r"(a[1]), "r"(a[2]), "r"(a[3]), "r"(b[0]), "r"(b[1]));
}

// Split two fp32 values into packed bf16x2 hi and lo words (x in low half).
__device__ __forceinline__ void split2(float x, float y, uint32_t& hi, uint32_t& lo) {
    __nv_bfloat16 hx = __float2bfloat16(x);
    __nv_bfloat16 hy = __float2bfloat16(y);
    __nv_bfloat16 lx = __float2bfloat16(x - __bfloat162float(hx));
    __nv_bfloat16 ly = __float2bfloat16(y - __bfloat162float(hy));
    __nv_bfloat162 h; h.x = hx; h.y = hy;
    __nv_bfloat162 l; l.x = lx; l.y = ly;
    hi = *reinterpret_cast<uint32_t*>(&h);
    lo = *reinterpret_cast<uint32_t*>(&l);
}

// Accurate-enough fast tanh: 2 MUFU (EX2 + RCP) + ~4 FMA, rel err ~1e-6
__device__ __forceinline__ float fast_tanh(float x) {
    float e = __expf(2.0f * x);
    return 1.0f - __fdividef(2.0f, e + 1.0f);
}

// ---------------------------------------------------------------------------
// Tensor-core NT GEMM (bf16x3 split, fp32-accurate to ~2^-17):
//   C[M,N] = A[M,K] * B[N,K]^T (+ bias[n])
// Block tile 128x64, K-chunk 32, 256 threads = 8 warps in 4x2 grid,
// warp tile 32x32. A/B staged in smem as hi/lo bf16 tiles, pitch 40.
// ---------------------------------------------------------------------------
#define APITCH 40

__global__ __launch_bounds__(256) void gemm_nt_tc(
    const float* __restrict__ A, const float* __restrict__ Bm,
    const float* __restrict__ bias, float* __restrict__ C,
    int M, int N, int K)
{
    __shared__ alignas(16) __nv_bfloat16 Ah[128 * APITCH];
    __shared__ alignas(16) __nv_bfloat16 Al[128 * APITCH];
    __shared__ alignas(16) __nv_bfloat16 Bh[64 * APITCH];
    __shared__ alignas(16) __nv_bfloat16 Bl[64 * APITCH];

    const int tid = threadIdx.x;
    const int lane = tid & 31;
    const int wid = tid >> 5;
    const int wm = wid >> 1;        // 0..3 (m direction)
    const int wn = wid & 1;         // 0..1 (n direction)
    const int m0 = blockIdx.y * 128;
    const int n0 = blockIdx.x * 64;

    // staging indices: one float4 per thread per pass
    const int ar = tid >> 3;            // 0..31
    const int ac = (tid & 7) << 2;      // 0,4,...,28

    // ldmatrix lane decomposition
    const int lq = lane >> 3;           // quadrant 0..3 (for x4)
    const int lr = lane & 7;
    const int bhalf = (lane >> 3) & 1;  // for x2 (lanes 0-15 used)
    const int br = lane & 7;

    float acc[2][4][4];
#pragma unroll
    for (int i = 0; i < 2; i++)
#pragma unroll
        for (int j = 0; j < 4; j++)
#pragma unroll
            for (int r = 0; r < 4; r++) acc[i][j][r] = 0.0f;

    for (int k0 = 0; k0 < K; k0 += 32) {
        // --- stage A tile 128x32 (hi/lo) ---
#pragma unroll
        for (int p = 0; p < 4; p++) {
            const int row = ar + 32 * p;
            const float4 v = *reinterpret_cast<const float4*>(
                &A[(size_t)(m0 + row) * K + k0 + ac]);
            uint32_t h0, l0, h1, l1;
            split2(v.x, v.y, h0, l0);
            split2(v.z, v.w, h1, l1);
            uint32_t* ph = reinterpret_cast<uint32_t*>(&Ah[row * APITCH + ac]);
            uint32_t* pl = reinterpret_cast<uint32_t*>(&Al[row * APITCH + ac]);
            ph[0] = h0; ph[1] = h1;
            pl[0] = l0; pl[1] = l1;
        }
        // --- stage B tile 64x32 (hi/lo) ---
#pragma unroll
        for (int p = 0; p < 2; p++) {
            const int row = ar + 32 * p;
            const float4 v = *reinterpret_cast<const float4*>(
                &Bm[(size_t)(n0 + row) * K + k0 + ac]);
            uint32_t h0, l0, h1, l1;
            split2(v.x, v.y, h0, l0);
            split2(v.z, v.w, h1, l1);
            uint32_t* ph = reinterpret_cast<uint32_t*>(&Bh[row * APITCH + ac]);
            uint32_t* pl = reinterpret_cast<uint32_t*>(&Bl[row * APITCH + ac]);
            ph[0] = h0; ph[1] = h1;
            pl[0] = l0; pl[1] = l1;
        }
        __syncthreads();

#pragma unroll
        for (int ks = 0; ks < 32; ks += 16) {
            uint32_t ah[2][4], al[2][4];
#pragma unroll
            for (int ma = 0; ma < 2; ma++) {
                const int m_local = wm * 32 + ma * 16 + (lq & 1) * 8 + lr;
                const int k_local = ks + (lq >> 1) * 8;
                ldsm_x4(ah[ma][0], ah[ma][1], ah[ma][2], ah[ma][3],
                        smem_u32(&Ah[m_local * APITCH + k_local]));
                ldsm_x4(al[ma][0], al[ma][1], al[ma][2], al[ma][3],
                        smem_u32(&Al[m_local * APITCH + k_local]));
            }
            uint32_t bh[4][2], bl[4][2];
#pragma unroll
            for (int na = 0; na < 4; na++) {
                const int n_local = wn * 32 + na * 8 + br;
                const int k_local = ks + bhalf * 8;
                ldsm_x2(bh[na][0], bh[na][1],
                        smem_u32(&Bh[n_local * APITCH + k_local]));
                ldsm_x2(bl[na][0], bl[na][1],
                        smem_u32(&Bl[n_local * APITCH + k_local]));
            }
#pragma unroll
            for (int ma = 0; ma < 2; ma++)
#pragma unroll
                for (int na = 0; na < 4; na++) {
                    mma_bf16(acc[ma][na], ah[ma], bh[na]);  // hi*hi
                    mma_bf16(acc[ma][na], ah[ma], bl[na]);  // hi*lo
                    mma_bf16(acc[ma][na], al[ma], bh[na]);  // lo*hi
                }
        }
        __syncthreads();
    }

    // epilogue
    const int er = lane >> 2;
    const int ec = (lane & 3) << 1;
#pragma unroll
    for (int ma = 0; ma < 2; ma++) {
        const int mbase = m0 + wm * 32 + ma * 16;
#pragma unroll
        for (int na = 0; na < 4; na++) {
            const int nbase = n0 + wn * 32 + na * 8 + ec;
            float b0 = 0.0f, b1 = 0.0f;
            if (bias) { b0 = bias[nbase]; b1 = bias[nbase + 1]; }
            float2 v0, v1;
            v0.x = acc[ma][na][0] + b0; v0.y = acc[ma][na][1] + b1;
            v1.x = acc[ma][na][2] + b0; v1.y = acc[ma][na][3] + b1;
            *reinterpret_cast<float2*>(&C[(size_t)(mbase + er) * N + nbase]) = v0;
            *reinterpret_cast<float2*>(&C[(size_t)(mbase + er + 8) * N + nbase]) = v1;
        }
    }
}

// ---------------------------------------------------------------------------
// Energies: E[b,q,v] = sum_n w[n] * tanh(Wh[b,q,n] + Uv[b,v,n])  (bias folded
// into Wh). Block tile: 32 q x 64 v, n-chunk 16, 256 threads, 2x4 per thread.
// MUFU-bound by design.
// ---------------------------------------------------------------------------
__global__ __launch_bounds__(256) void energy_kernel(
    const float* __restrict__ Wh, const float* __restrict__ Uv,
    const float* __restrict__ w, float* __restrict__ energies)
{
    __shared__ float As[16][33];   // [kk][q]
    __shared__ float Cs[16][65];   // [kk][v]
    __shared__ float ws[16];

    const int b = blockIdx.z;
    const int q0 = blockIdx.y * 32;
    const int v0 = blockIdx.x * 64;
    const int tid = threadIdx.x;
    const int tx = tid & 15, ty = tid >> 4;

    const float* Ab = Wh + ((size_t)b * LQ + q0) * BN;
    const float* Cb = Uv + ((size_t)b * LV + v0) * BN;

    float acc[2][4];
#pragma unroll
    for (int i = 0; i < 2; i++)
#pragma unroll
        for (int j = 0; j < 4; j++) acc[i][j] = 0.0f;

    for (int k0 = 0; k0 < BN; k0 += 16) {
#pragma unroll
        for (int e = 0; e < 2; e++) {           // 32q x 16k
            int id = tid + e * 256;
            int q = id >> 4, kk = id & 15;
            As[kk][q] = Ab[(size_t)q * BN + k0 + kk];
        }
#pragma unroll
        for (int e = 0; e < 4; e++) {           // 64v x 16k
            int id = tid + e * 256;
            int v = id >> 4, kk = id & 15;
            Cs[kk][v] = Cb[(size_t)v * BN + k0 + kk];
        }
        if (tid < 16) ws[tid] = w[k0 + tid];
        __syncthreads();
#pragma unroll
        for (int kk = 0; kk < 16; kk++) {
            float wn = ws[kk];
            float a0 = As[kk][ty];
            float a1 = As[kk][ty + 16];
            float c[4];
#pragma unroll
            for (int j = 0; j < 4; j++) c[j] = Cs[kk][tx + 16 * j];
#pragma unroll
            for (int j = 0; j < 4; j++) {
                acc[0][j] += wn * fast_tanh(a0 + c[j]);
                acc[1][j] += wn * fast_tanh(a1 + c[j]);
            }
        }
        __syncthreads();
    }
#pragma unroll
    for (int i = 0; i < 2; i++) {
        int q = q0 + ty + 16 * i;
#pragma unroll
        for (int j = 0; j < 4; j++) {
            int v = v0 + tx + 16 * j;
            energies[((size_t)b * LQ + q) * LV + v] = acc[i][j];
        }
    }
}

// ---------------------------------------------------------------------------
// Softmax over v=128, one warp per (b,q) row.
// ---------------------------------------------------------------------------
__global__ __launch_bounds__(256) void softmax_kernel(
    const float* __restrict__ energies, float* __restrict__ weights)
{
    const int warps_per_blk = blockDim.x >> 5;
    const int row = blockIdx.x * warps_per_blk + (threadIdx.x >> 5);
    const int lane = threadIdx.x & 31;
    if (row >= NB * LQ) return;
    const float* e = energies + (size_t)row * LV;

    float v[4];
    float mx = -1e30f;
#pragma unroll
    for (int j = 0; j < 4; j++) { v[j] = e[lane + 32 * j]; mx = fmaxf(mx, v[j]); }
#pragma unroll
    for (int o = 16; o > 0; o >>= 1) mx = fmaxf(mx, __shfl_xor_sync(0xFFFFFFFFu, mx, o));
    float s = 0.0f;
#pragma unroll
    for (int j = 0; j < 4; j++) { v[j] = __expf(v[j] - mx); s += v[j]; }
#pragma unroll
    for (int o = 16; o > 0; o >>= 1) s += __shfl_xor_sync(0xFFFFFFFFu, s, o);
    float inv = __fdividef(1.0f, s);
#pragma unroll
    for (int j = 0; j < 4; j++) weights[(size_t)row * LV + lane + 32 * j] = v[j] * inv;
}

// ---------------------------------------------------------------------------
// aligned[b,q,f] = sum_v weights[b,q,v] * vis[b,v,f]; written into the
// concat output at column offset QS.
// ---------------------------------------------------------------------------
__global__ __launch_bounds__(256) void aligned_kernel(
    const float* __restrict__ weights, const float* __restrict__ vis,
    float* __restrict__ out_sem)
{
    __shared__ float Ws[LQ][LV];     // 32 KB
    __shared__ float Vs[16][64];     // 4 KB
    const int b = blockIdx.y;
    const int f0 = blockIdx.x * 64;
    const int tid = threadIdx.x;
    const int tx = tid & 15, ty = tid >> 4;

#pragma unroll
    for (int e = 0; e < 32; e++) {
        int id = tid + e * 256;
        Ws[id >> 7][id & 127] = weights[(size_t)b * LQ * LV + id];
    }

    float acc[4][4];
#pragma unroll
    for (int i = 0; i < 4; i++)
#pragma unroll
        for (int j = 0; j < 4; j++) acc[i][j] = 0.0f;

    for (int k0 = 0; k0 < LV; k0 += 16) {
        __syncthreads();
#pragma unroll
        for (int e = 0; e < 4; e++) {
            int id = tid + e * 256;
            int kk = id >> 6, f = id & 63;
            Vs[kk][f] = vis[((size_t)b * LV + k0 + kk) * FS + f0 + f];
        }
        __syncthreads();
#pragma unroll
        for (int kk = 0; kk < 16; kk++) {
            float wv[4], vv[4];
#pragma unroll
            for (int i = 0; i < 4; i++) wv[i] = Ws[ty + 16 * i][k0 + kk];
#pragma unroll
            for (int j = 0; j < 4; j++) vv[j] = Vs[kk][tx + 16 * j];
#pragma unroll
            for (int i = 0; i < 4; i++)
#pragma unroll
                for (int j = 0; j < 4; j++)
                    acc[i][j] += wv[i] * vv[j];
        }
    }
#pragma unroll
    for (int i = 0; i < 4; i++) {
        int q = ty + 16 * i;
#pragma unroll
        for (int j = 0; j < 4; j++) {
            int f = f0 + tx + 16 * j;
            out_sem[((size_t)b * LQ + q) * (QS + FS) + QS + f] = acc[i][j];
        }
    }
}

// Copy phr_feats into concat output columns [0, QS)
__global__ __launch_bounds__(256) void copy_phr_kernel(
    const float* __restrict__ phr, float* __restrict__ out_sem)
{
    const size_t total4 = (size_t)NB * LQ * QS / 4;
    for (size_t i = (size_t)blockIdx.x * blockDim.x + threadIdx.x; i < total4;
         i += (size_t)gridDim.x * blockDim.x) {
        size_t elem = i * 4;
        size_t row = elem >> 9;
        size_t c = elem & 511;
        float4 v = *reinterpret_cast<const float4*>(phr + elem);
        *reinterpret_cast<float4*>(out_sem + row * (QS + FS) + c) = v;
    }
}

extern "C" void kernel_launch(void* const* d_in, const int* in_sizes, int n_in,
                              void* d_out, int out_size)
{
    const float* phr  = (const float*)d_in[0];  // [32,64,512]
    const float* vis  = (const float*)d_in[1];  // [32,128,1024]
    const float* W    = (const float*)d_in[2];  // [512,512]
    const float* U    = (const float*)d_in[3];  // [512,1024]
    const float* bias = (const float*)d_in[4];  // [512]
    const float* w    = (const float*)d_in[5];  // [1,512]

    float* out = (float*)d_out;
    float* out_sem = out;
    float* out_w   = out + (size_t)NB * LQ * (QS + FS);
    float* out_e   = out_w + (size_t)NB * LQ * LV;

    float* Wh = nullptr;
    float* Uv = nullptr;
    cudaGetSymbolAddress((void**)&Wh, g_Wh);
    cudaGetSymbolAddress((void**)&Uv, g_Uv);

    // Wh = phr @ W^T + b    (M=2048, N=512, K=512) — tensor core bf16x3
    gemm_nt_tc<<<dim3(BN / 64, (NB * LQ) / 128), 256>>>(phr, W, bias, Wh,
                                                        NB * LQ, BN, QS);
    // Uv = vis @ U^T        (M=4096, N=512, K=1024) — tensor core bf16x3
    gemm_nt_tc<<<dim3(BN / 64, (NB * LV) / 128), 256>>>(vis, U, nullptr, Uv,
                                                        NB * LV, BN, FS);
    // energies
    energy_kernel<<<dim3(LV / 64, LQ / 32, NB), 256>>>(Wh, Uv, w, out_e);
    // softmax over v
    softmax_kernel<<<(NB * LQ) / 8, 256>>>(out_e, out_w);
    // aligned + concat
    aligned_kernel<<<dim3(FS / 64, NB), 256>>>(out_w, vis, out_sem);
    copy_phr_kernel<<<1024, 256>>>(phr, out_sem);
}

// round 3
// speedup vs baseline: 2.3535x; 1.2424x over previous
#include <cuda_runtime.h>
#include <cuda_bf16.h>
#include <cstdint>
#include <cstddef>

#define NB 32
#define LQ 64
#define LV 128
#define QS 512
#define FS 1024
#define BN 512

// Scratch (device globals — no allocation)
__device__ float g_Wh[(size_t)NB * LQ * BN];   // Wh + bias, [b*LQ+q][n]
__device__ float g_Uv[(size_t)NB * LV * BN];   // Uv,        [b*LV+v][n]

// ---------------------------------------------------------------------------
// Helpers
// ---------------------------------------------------------------------------
__device__ __forceinline__ uint32_t smem_u32(const void* p) {
    return (uint32_t)__cvta_generic_to_shared(p);
}

__device__ __forceinline__ void ldsm_x4(uint32_t& r0, uint32_t& r1,
                                        uint32_t& r2, uint32_t& r3, uint32_t addr) {
    asm volatile("ldmatrix.sync.aligned.m8n8.x4.shared.b16 {%0,%1,%2,%3}, [%4];"
                 : "=r"(r0), "=r"(r1), "=r"(r2), "=r"(r3) : "r"(addr));
}

__device__ __forceinline__ void ldsm_x2(uint32_t& r0, uint32_t& r1, uint32_t addr) {
    asm volatile("ldmatrix.sync.aligned.m8n8.x2.shared.b16 {%0,%1}, [%2];"
                 : "=r"(r0), "=r"(r1) : "r"(addr));
}

__device__ __forceinline__ void mma_bf16(float* d, const uint32_t* a, const uint32_t* b) {
    asm volatile(
        "mma.sync.aligned.m16n8k16.row.col.f32.bf16.bf16.f32 "
        "{%0,%1,%2,%3}, {%4,%5,%6,%7}, {%8,%9}, {%0,%1,%2,%3};"
        : "+f"(d[0]), "+f"(d[1]), "+f"(d[2]), "+f"(d[3])
        : "r"(a[0]), "r"(a[1]), "r"(a[2]), "r"(a[3]), "r"(b[0]), "r"(b[1]));
}

// Split two fp32 values into packed bf16x2 hi and lo words (x in low half).
__device__ __forceinline__ void split2(float x, float y, uint32_t& hi, uint32_t& lo) {
    __nv_bfloat16 hx = __float2bfloat16(x);
    __nv_bfloat16 hy = __float2bfloat16(y);
    __nv_bfloat16 lx = __float2bfloat16(x - __bfloat162float(hx));
    __nv_bfloat16 ly = __float2bfloat16(y - __bfloat162float(hy));
    __nv_bfloat162 h; h.x = hx; h.y = hy;
    __nv_bfloat162 l; l.x = lx; l.y = ly;
    hi = *reinterpret_cast<uint32_t*>(&h);
    lo = *reinterpret_cast<uint32_t*>(&l);
}

// Hardware tanh: 1 MUFU op (sm_75+), rel err ~2^-11
__device__ __forceinline__ float tanh_fast(float x) {
    float y;
    asm("tanh.approx.f32 %0, %1;" : "=f"(y) : "f"(x));
    return y;
}

// ---------------------------------------------------------------------------
// Tensor-core NT GEMM (bf16x3 split): C[M,N] = A[M,K] * B[N,K]^T (+ bias[n])
// Block tile 128x64, K-chunk 32, 256 threads = 8 warps (4x2), warp tile 32x32.
// ---------------------------------------------------------------------------
#define APITCH 40

__global__ __launch_bounds__(256) void gemm_nt_tc(
    const float* __restrict__ A, const float* __restrict__ Bm,
    const float* __restrict__ bias, float* __restrict__ C,
    int M, int N, int K)
{
    __shared__ alignas(16) __nv_bfloat16 Ah[128 * APITCH];
    __shared__ alignas(16) __nv_bfloat16 Al[128 * APITCH];
    __shared__ alignas(16) __nv_bfloat16 Bh[64 * APITCH];
    __shared__ alignas(16) __nv_bfloat16 Bl[64 * APITCH];

    const int tid = threadIdx.x;
    const int lane = tid & 31;
    const int wid = tid >> 5;
    const int wm = wid >> 1;
    const int wn = wid & 1;
    const int m0 = blockIdx.y * 128;
    const int n0 = blockIdx.x * 64;

    const int ar = tid >> 3;
    const int ac = (tid & 7) << 2;

    const int lq = lane >> 3;
    const int lr = lane & 7;
    const int bhalf = (lane >> 3) & 1;
    const int br = lane & 7;

    float acc[2][4][4];
#pragma unroll
    for (int i = 0; i < 2; i++)
#pragma unroll
        for (int j = 0; j < 4; j++)
#pragma unroll
            for (int r = 0; r < 4; r++) acc[i][j][r] = 0.0f;

    for (int k0 = 0; k0 < K; k0 += 32) {
#pragma unroll
        for (int p = 0; p < 4; p++) {
            const int row = ar + 32 * p;
            const float4 v = *reinterpret_cast<const float4*>(
                &A[(size_t)(m0 + row) * K + k0 + ac]);
            uint32_t h0, l0, h1, l1;
            split2(v.x, v.y, h0, l0);
            split2(v.z, v.w, h1, l1);
            uint32_t* ph = reinterpret_cast<uint32_t*>(&Ah[row * APITCH + ac]);
            uint32_t* pl = reinterpret_cast<uint32_t*>(&Al[row * APITCH + ac]);
            ph[0] = h0; ph[1] = h1;
            pl[0] = l0; pl[1] = l1;
        }
#pragma unroll
        for (int p = 0; p < 2; p++) {
            const int row = ar + 32 * p;
            const float4 v = *reinterpret_cast<const float4*>(
                &Bm[(size_t)(n0 + row) * K + k0 + ac]);
            uint32_t h0, l0, h1, l1;
            split2(v.x, v.y, h0, l0);
            split2(v.z, v.w, h1, l1);
            uint32_t* ph = reinterpret_cast<uint32_t*>(&Bh[row * APITCH + ac]);
            uint32_t* pl = reinterpret_cast<uint32_t*>(&Bl[row * APITCH + ac]);
            ph[0] = h0; ph[1] = h1;
            pl[0] = l0; pl[1] = l1;
        }
        __syncthreads();

#pragma unroll
        for (int ks = 0; ks < 32; ks += 16) {
            uint32_t ah[2][4], al[2][4];
#pragma unroll
            for (int ma = 0; ma < 2; ma++) {
                const int m_local = wm * 32 + ma * 16 + (lq & 1) * 8 + lr;
                const int k_local = ks + (lq >> 1) * 8;
                ldsm_x4(ah[ma][0], ah[ma][1], ah[ma][2], ah[ma][3],
                        smem_u32(&Ah[m_local * APITCH + k_local]));
                ldsm_x4(al[ma][0], al[ma][1], al[ma][2], al[ma][3],
                        smem_u32(&Al[m_local * APITCH + k_local]));
            }
            uint32_t bh[4][2], bl[4][2];
#pragma unroll
            for (int na = 0; na < 4; na++) {
                const int n_local = wn * 32 + na * 8 + br;
                const int k_local = ks + bhalf * 8;
                ldsm_x2(bh[na][0], bh[na][1],
                        smem_u32(&Bh[n_local * APITCH + k_local]));
                ldsm_x2(bl[na][0], bl[na][1],
                        smem_u32(&Bl[n_local * APITCH + k_local]));
            }
#pragma unroll
            for (int ma = 0; ma < 2; ma++)
#pragma unroll
                for (int na = 0; na < 4; na++) {
                    mma_bf16(acc[ma][na], ah[ma], bh[na]);
                    mma_bf16(acc[ma][na], ah[ma], bl[na]);
                    mma_bf16(acc[ma][na], al[ma], bh[na]);
                }
        }
        __syncthreads();
    }

    const int er = lane >> 2;
    const int ec = (lane & 3) << 1;
#pragma unroll
    for (int ma = 0; ma < 2; ma++) {
        const int mbase = m0 + wm * 32 + ma * 16;
#pragma unroll
        for (int na = 0; na < 4; na++) {
            const int nbase = n0 + wn * 32 + na * 8 + ec;
            float b0 = 0.0f, b1 = 0.0f;
            if (bias) { b0 = bias[nbase]; b1 = bias[nbase + 1]; }
            float2 v0, v1;
            v0.x = acc[ma][na][0] + b0; v0.y = acc[ma][na][1] + b1;
            v1.x = acc[ma][na][2] + b0; v1.y = acc[ma][na][3] + b1;
            *reinterpret_cast<float2*>(&C[(size_t)(mbase + er) * N + nbase]) = v0;
            *reinterpret_cast<float2*>(&C[(size_t)(mbase + er + 8) * N + nbase]) = v1;
        }
    }
}

// ---------------------------------------------------------------------------
// Fused energies + softmax.
// E[b,q,v] = sum_n w[n] * tanh(Wh[b,q,n] + Uv[b,v,n])  (bias folded into Wh)
// Block tile: 8 q x 128 v (full v-row per warp). warp = q row, lane = 4 v's.
// After the n loop each warp does an in-register softmax and writes both
// energies and weights. MUFU-bound (1 tanh.approx per element).
// ---------------------------------------------------------------------------
#define QT 8

__global__ __launch_bounds__(256) void energy_softmax_kernel(
    const float* __restrict__ Wh, const float* __restrict__ Uv,
    const float* __restrict__ w,
    float* __restrict__ energies, float* __restrict__ weights)
{
    __shared__ float As[16][QT];     // [kk][q]
    __shared__ float Cs[16][132];    // [kk][v], padded pitch
    __shared__ float ws[BN];

    const int b = blockIdx.y;
    const int q0 = blockIdx.x * QT;
    const int tid = threadIdx.x;
    const int lane = tid & 31;
    const int ty = tid >> 5;         // warp id = local q row

    const float* Ab = Wh + ((size_t)b * LQ + q0) * BN;
    const float* Cb = Uv + (size_t)b * LV * BN;

    for (int i = tid; i < BN; i += 256) ws[i] = w[i];

    float acc[4] = {0.0f, 0.0f, 0.0f, 0.0f};

    for (int k0 = 0; k0 < BN; k0 += 16) {
        if (tid < 128) {                      // 8q x 16k
            const int q = tid >> 4, kk = tid & 15;
            As[kk][q] = Ab[(size_t)q * BN + k0 + kk];
        }
#pragma unroll
        for (int e = 0; e < 8; e++) {         // 128v x 16k
            const int id = tid + e * 256;
            const int v = id >> 4, kk = id & 15;
            Cs[kk][v] = Cb[(size_t)v * BN + k0 + kk];
        }
        __syncthreads();
#pragma unroll
        for (int kk = 0; kk < 16; kk++) {
            const float a = As[kk][ty];       // broadcast within warp
            const float wn = ws[k0 + kk];
#pragma unroll
            for (int j = 0; j < 4; j++) {
                acc[j] += wn * tanh_fast(a + Cs[kk][lane + 32 * j]);
            }
        }
        __syncthreads();
    }

    // warp-level softmax over the 128 v values (4 per lane)
    float mx = fmaxf(fmaxf(acc[0], acc[1]), fmaxf(acc[2], acc[3]));
#pragma unroll
    for (int o = 16; o > 0; o >>= 1) mx = fmaxf(mx, __shfl_xor_sync(0xFFFFFFFFu, mx, o));
    float ex[4], s = 0.0f;
#pragma unroll
    for (int j = 0; j < 4; j++) { ex[j] = __expf(acc[j] - mx); s += ex[j]; }
#pragma unroll
    for (int o = 16; o > 0; o >>= 1) s += __shfl_xor_sync(0xFFFFFFFFu, s, o);
    const float inv = __fdividef(1.0f, s);

    const size_t row = (size_t)b * LQ + q0 + ty;
#pragma unroll
    for (int j = 0; j < 4; j++) {
        energies[row * LV + lane + 32 * j] = acc[j];
        weights[row * LV + lane + 32 * j] = ex[j] * inv;
    }
}

// ---------------------------------------------------------------------------
// aligned[b,q,f] = sum_v weights[b,q,v] * vis[b,v,f] -> out columns [QS,QS+FS)
// Extra blockIdx.x tiles (>= FS/64) copy phr_feats into columns [0, QS).
// ---------------------------------------------------------------------------
__global__ __launch_bounds__(256) void aligned_concat_kernel(
    const float* __restrict__ weights, const float* __restrict__ vis,
    const float* __restrict__ phr, float* __restrict__ out_sem)
{
    const int b = blockIdx.y;
    const int tid = threadIdx.x;

    if (blockIdx.x >= FS / 64) {
        // copy tile: 64 q rows x 64 phr columns
        const int c0 = (blockIdx.x - FS / 64) * 64;
#pragma unroll
        for (int e = 0; e < 4; e++) {
            const int id = tid + e * 256;          // 0..1023 float4s
            const int q = id >> 4;                 // 64 rows
            const int c = (id & 15) << 2;          // 0..60
            const float4 v = *reinterpret_cast<const float4*>(
                &phr[((size_t)b * LQ + q) * QS + c0 + c]);
            *reinterpret_cast<float4*>(
                &out_sem[((size_t)b * LQ + q) * (QS + FS) + c0 + c]) = v;
        }
        return;
    }

    __shared__ float Ws[LQ][LV];     // 32 KB
    __shared__ float Vs[16][64];     // 4 KB
    const int f0 = blockIdx.x * 64;
    const int tx = tid & 15, ty = tid >> 4;

#pragma unroll
    for (int e = 0; e < 32; e++) {
        int id = tid + e * 256;
        Ws[id >> 7][id & 127] = weights[(size_t)b * LQ * LV + id];
    }

    float acc[4][4];
#pragma unroll
    for (int i = 0; i < 4; i++)
#pragma unroll
        for (int j = 0; j < 4; j++) acc[i][j] = 0.0f;

    for (int k0 = 0; k0 < LV; k0 += 16) {
        __syncthreads();
#pragma unroll
        for (int e = 0; e < 4; e++) {
            int id = tid + e * 256;
            int kk = id >> 6, f = id & 63;
            Vs[kk][f] = vis[((size_t)b * LV + k0 + kk) * FS + f0 + f];
        }
        __syncthreads();
#pragma unroll
        for (int kk = 0; kk < 16; kk++) {
            float wv[4], vv[4];
#pragma unroll
            for (int i = 0; i < 4; i++) wv[i] = Ws[ty + 16 * i][k0 + kk];
#pragma unroll
            for (int j = 0; j < 4; j++) vv[j] = Vs[kk][tx + 16 * j];
#pragma unroll
            for (int i = 0; i < 4; i++)
#pragma unroll
                for (int j = 0; j < 4; j++)
                    acc[i][j] += wv[i] * vv[j];
        }
    }
#pragma unroll
    for (int i = 0; i < 4; i++) {
        int q = ty + 16 * i;
#pragma unroll
        for (int j = 0; j < 4; j++) {
            int f = f0 + tx + 16 * j;
            out_sem[((size_t)b * LQ + q) * (QS + FS) + QS + f] = acc[i][j];
        }
    }
}

extern "C" void kernel_launch(void* const* d_in, const int* in_sizes, int n_in,
                              void* d_out, int out_size)
{
    const float* phr  = (const float*)d_in[0];  // [32,64,512]
    const float* vis  = (const float*)d_in[1];  // [32,128,1024]
    const float* W    = (const float*)d_in[2];  // [512,512]
    const float* U    = (const float*)d_in[3];  // [512,1024]
    const float* bias = (const float*)d_in[4];  // [512]
    const float* w    = (const float*)d_in[5];  // [1,512]

    float* out = (float*)d_out;
    float* out_sem = out;
    float* out_w   = out + (size_t)NB * LQ * (QS + FS);
    float* out_e   = out_w + (size_t)NB * LQ * LV;

    float* Wh = nullptr;
    float* Uv = nullptr;
    cudaGetSymbolAddress((void**)&Wh, g_Wh);
    cudaGetSymbolAddress((void**)&Uv, g_Uv);

    // Wh = phr @ W^T + b    (M=2048, N=512, K=512)
    gemm_nt_tc<<<dim3(BN / 64, (NB * LQ) / 128), 256>>>(phr, W, bias, Wh,
                                                        NB * LQ, BN, QS);
    // Uv = vis @ U^T        (M=4096, N=512, K=1024)
    gemm_nt_tc<<<dim3(BN / 64, (NB * LV) / 128), 256>>>(vis, U, nullptr, Uv,
                                                        NB * LV, BN, FS);
    // energies + softmax fused
    energy_softmax_kernel<<<dim3(LQ / QT, NB), 256>>>(Wh, Uv, w, out_e, out_w);
    // aligned + concat (incl. phr copy tiles)
    aligned_concat_kernel<<<dim3(FS / 64 + QS / 64, NB), 256>>>(out_w, vis, phr,
                                                                out_sem);
}

// round 4
// speedup vs baseline: 2.3983x; 1.0191x over previous
#include <cuda_runtime.h>
#include <cuda_bf16.h>
#include <cstdint>
#include <cstddef>

#define NB 32
#define LQ 64
#define LV 128
#define QS 512
#define FS 1024
#define BN 512

// ---------------- scratch (device globals — no allocation) ----------------
__device__ float g_Wh[(size_t)NB * LQ * BN];
__device__ float g_Uv[(size_t)NB * LV * BN];
__device__ __nv_bfloat16 g_phr_hi[(size_t)NB * LQ * QS];
__device__ __nv_bfloat16 g_phr_lo[(size_t)NB * LQ * QS];
__device__ __nv_bfloat16 g_vis_hi[(size_t)NB * LV * FS];
__device__ __nv_bfloat16 g_vis_lo[(size_t)NB * LV * FS];
__device__ __nv_bfloat16 g_W_hi[(size_t)BN * QS];
__device__ __nv_bfloat16 g_W_lo[(size_t)BN * QS];
__device__ __nv_bfloat16 g_U_hi[(size_t)BN * FS];
__device__ __nv_bfloat16 g_U_lo[(size_t)BN * FS];
__device__ __nv_bfloat16 g_wt_hi[(size_t)NB * LQ * LV];
__device__ __nv_bfloat16 g_wt_lo[(size_t)NB * LQ * LV];

// ---------------------------------------------------------------------------
// Helpers
// ---------------------------------------------------------------------------
__device__ __forceinline__ uint32_t smem_u32(const void* p) {
    return (uint32_t)__cvta_generic_to_shared(p);
}

__device__ __forceinline__ void cpasync16(void* s, const void* g) {
    asm volatile("cp.async.cg.shared.global [%0], [%1], 16;"
                 :: "r"(smem_u32(s)), "l"(g));
}

__device__ __forceinline__ void ldsm_x4(uint32_t& r0, uint32_t& r1,
                                        uint32_t& r2, uint32_t& r3, uint32_t addr) {
    asm volatile("ldmatrix.sync.aligned.m8n8.x4.shared.b16 {%0,%1,%2,%3}, [%4];"
                 : "=r"(r0), "=r"(r1), "=r"(r2), "=r"(r3) : "r"(addr));
}

__device__ __forceinline__ void ldsm_x4_t(uint32_t& r0, uint32_t& r1,
                                          uint32_t& r2, uint32_t& r3, uint32_t addr) {
    asm volatile("ldmatrix.sync.aligned.m8n8.x4.trans.shared.b16 {%0,%1,%2,%3}, [%4];"
                 : "=r"(r0), "=r"(r1), "=r"(r2), "=r"(r3) : "r"(addr));
}

__device__ __forceinline__ void ldsm_x2(uint32_t& r0, uint32_t& r1, uint32_t addr) {
    asm volatile("ldmatrix.sync.aligned.m8n8.x2.shared.b16 {%0,%1}, [%2];"
                 : "=r"(r0), "=r"(r1) : "r"(addr));
}

__device__ __forceinline__ void mma_bf16(float* d, const uint32_t* a, const uint32_t* b) {
    asm volatile(
        "mma.sync.aligned.m16n8k16.row.col.f32.bf16.bf16.f32 "
        "{%0,%1,%2,%3}, {%4,%5,%6,%7}, {%8,%9}, {%0,%1,%2,%3};"
        : "+f"(d[0]), "+f"(d[1]), "+f"(d[2]), "+f"(d[3])
        : "r"(a[0]), "r"(a[1]), "r"(a[2]), "r"(a[3]), "r"(b[0]), "r"(b[1]));
}

// Hardware tanh: 1 MUFU op, rel err ~2^-11 (validated: net rel_err 5e-6)
__device__ __forceinline__ float tanh_fast(float x) {
    float y;
    asm("tanh.approx.f32 %0, %1;" : "=f"(y) : "f"(x));
    return y;
}

// ---------------------------------------------------------------------------
// Split pass: fp32 -> (hi, lo) bf16 for 4 arrays in one launch.
// Sizes given in float4 units; total threads = sum exactly.
// ---------------------------------------------------------------------------
__global__ __launch_bounds__(256) void split4_kernel(
    const float* __restrict__ s0, __nv_bfloat16* __restrict__ h0, __nv_bfloat16* __restrict__ l0, int n0,
    const float* __restrict__ s1, __nv_bfloat16* __restrict__ h1, __nv_bfloat16* __restrict__ l1, int n1,
    const float* __restrict__ s2, __nv_bfloat16* __restrict__ h2, __nv_bfloat16* __restrict__ l2, int n2,
    const float* __restrict__ s3, __nv_bfloat16* __restrict__ h3, __nv_bfloat16* __restrict__ l3, int n3)
{
    int i = blockIdx.x * 256 + threadIdx.x;
    const float* s; __nv_bfloat16 *h, *l; int idx;
    if (i < n0)                { s = s0; h = h0; l = l0; idx = i; }
    else if (i < n0 + n1)      { s = s1; h = h1; l = l1; idx = i - n0; }
    else if (i < n0 + n1 + n2) { s = s2; h = h2; l = l2; idx = i - n0 - n1; }
    else                       { s = s3; h = h3; l = l3; idx = i - n0 - n1 - n2; }

    float4 v = reinterpret_cast<const float4*>(s)[idx];
    __nv_bfloat162 ha, hb, la, lb;
    ha.x = __float2bfloat16(v.x); ha.y = __float2bfloat16(v.y);
    hb.x = __float2bfloat16(v.z); hb.y = __float2bfloat16(v.w);
    la.x = __float2bfloat16(v.x - __bfloat162float(ha.x));
    la.y = __float2bfloat16(v.y - __bfloat162float(ha.y));
    lb.x = __float2bfloat16(v.z - __bfloat162float(hb.x));
    lb.y = __float2bfloat16(v.w - __bfloat162float(hb.y));
    reinterpret_cast<__nv_bfloat162*>(h)[2 * idx]     = ha;
    reinterpret_cast<__nv_bfloat162*>(h)[2 * idx + 1] = hb;
    reinterpret_cast<__nv_bfloat162*>(l)[2 * idx]     = la;
    reinterpret_cast<__nv_bfloat162*>(l)[2 * idx + 1] = lb;
}

// ---------------------------------------------------------------------------
// Tensor-core NT GEMM on pre-split bf16 hi/lo, cp.async 2-stage pipeline.
//   C[M,N] = A[M,K] * B[N,K]^T (+ bias)   (bf16x3: hh + hl + lh)
// Block 128x64, KC=32, 256 threads = 8 warps (4x2), warp tile 32x32.
// Dynamic smem: 2 stages x (128+128+64+64) rows x 40 halves = 61440 B.
// ---------------------------------------------------------------------------
#define APITCH 40
#define KC 32
#define GSTAGE (384 * APITCH)   // halves per stage

__device__ __forceinline__ void gemm_issue_stage(
    __nv_bfloat16* smem, int st, int tid, int m0, int n0, int k0, int K,
    const __nv_bfloat16* Ahi, const __nv_bfloat16* Alo,
    const __nv_bfloat16* Bhi, const __nv_bfloat16* Blo)
{
    __nv_bfloat16* base = smem + st * GSTAGE;
#pragma unroll
    for (int e = 0; e < 2; e++) {                 // A: 512 chunks hi + 512 lo
        int idx = tid + e * 256;
        int row = idx >> 2, c = (idx & 3) * 8;
        cpasync16(&base[row * APITCH + c], &Ahi[(size_t)(m0 + row) * K + k0 + c]);
        cpasync16(&base[128 * APITCH + row * APITCH + c],
                  &Alo[(size_t)(m0 + row) * K + k0 + c]);
    }
    {                                             // B: 256 chunks hi + 256 lo
        int row = tid >> 2, c = (tid & 3) * 8;
        cpasync16(&base[256 * APITCH + row * APITCH + c],
                  &Bhi[(size_t)(n0 + row) * K + k0 + c]);
        cpasync16(&base[320 * APITCH + row * APITCH + c],
                  &Blo[(size_t)(n0 + row) * K + k0 + c]);
    }
    asm volatile("cp.async.commit_group;");
}

__global__ __launch_bounds__(256) void gemm_nt_bf16x3(
    const __nv_bfloat16* __restrict__ Ahi, const __nv_bfloat16* __restrict__ Alo,
    const __nv_bfloat16* __restrict__ Bhi, const __nv_bfloat16* __restrict__ Blo,
    const float* __restrict__ bias, float* __restrict__ C,
    int M, int N, int K)
{
    extern __shared__ __nv_bfloat16 gsm[];

    const int tid = threadIdx.x;
    const int lane = tid & 31;
    const int wid = tid >> 5;
    const int wm = wid >> 1;
    const int wn = wid & 1;
    const int m0 = blockIdx.y * 128;
    const int n0 = blockIdx.x * 64;

    const int lq = lane >> 3;
    const int lr = lane & 7;
    const int bhalf = (lane >> 3) & 1;
    const int br = lane & 7;

    float acc[2][4][4];
#pragma unroll
    for (int i = 0; i < 2; i++)
#pragma unroll
        for (int j = 0; j < 4; j++)
#pragma unroll
            for (int r = 0; r < 4; r++) acc[i][j][r] = 0.0f;

    const int NC = K / KC;
    gemm_issue_stage(gsm, 0, tid, m0, n0, 0, K, Ahi, Alo, Bhi, Blo);

    for (int c = 0; c < NC; c++) {
        const int st = c & 1;
        if (c + 1 < NC) {
            gemm_issue_stage(gsm, st ^ 1, tid, m0, n0, (c + 1) * KC, K,
                             Ahi, Alo, Bhi, Blo);
            asm volatile("cp.async.wait_group 1;" ::: "memory");
        } else {
            asm volatile("cp.async.wait_group 0;" ::: "memory");
        }
        __syncthreads();

        const __nv_bfloat16* Ah_s = gsm + st * GSTAGE;
        const __nv_bfloat16* Al_s = Ah_s + 128 * APITCH;
        const __nv_bfloat16* Bh_s = Ah_s + 256 * APITCH;
        const __nv_bfloat16* Bl_s = Ah_s + 320 * APITCH;

#pragma unroll
        for (int ks = 0; ks < KC; ks += 16) {
            uint32_t ah[2][4], al[2][4];
#pragma unroll
            for (int ma = 0; ma < 2; ma++) {
                const int m_local = wm * 32 + ma * 16 + (lq & 1) * 8 + lr;
                const int k_local = ks + (lq >> 1) * 8;
                ldsm_x4(ah[ma][0], ah[ma][1], ah[ma][2], ah[ma][3],
                        smem_u32(&Ah_s[m_local * APITCH + k_local]));
                ldsm_x4(al[ma][0], al[ma][1], al[ma][2], al[ma][3],
                        smem_u32(&Al_s[m_local * APITCH + k_local]));
            }
            uint32_t bh[4][2], bl[4][2];
#pragma unroll
            for (int na = 0; na < 4; na++) {
                const int n_local = wn * 32 + na * 8 + br;
                const int k_local = ks + bhalf * 8;
                ldsm_x2(bh[na][0], bh[na][1],
                        smem_u32(&Bh_s[n_local * APITCH + k_local]));
                ldsm_x2(bl[na][0], bl[na][1],
                        smem_u32(&Bl_s[n_local * APITCH + k_local]));
            }
#pragma unroll
            for (int ma = 0; ma < 2; ma++)
#pragma unroll
                for (int na = 0; na < 4; na++) {
                    mma_bf16(acc[ma][na], ah[ma], bh[na]);
                    mma_bf16(acc[ma][na], ah[ma], bl[na]);
                    mma_bf16(acc[ma][na], al[ma], bh[na]);
                }
        }
        __syncthreads();
    }

    const int er = lane >> 2;
    const int ec = (lane & 3) << 1;
#pragma unroll
    for (int ma = 0; ma < 2; ma++) {
        const int mbase = m0 + wm * 32 + ma * 16;
#pragma unroll
        for (int na = 0; na < 4; na++) {
            const int nbase = n0 + wn * 32 + na * 8 + ec;
            float b0 = 0.0f, b1 = 0.0f;
            if (bias) { b0 = bias[nbase]; b1 = bias[nbase + 1]; }
            float2 v0, v1;
            v0.x = acc[ma][na][0] + b0; v0.y = acc[ma][na][1] + b1;
            v1.x = acc[ma][na][2] + b0; v1.y = acc[ma][na][3] + b1;
            *reinterpret_cast<float2*>(&C[(size_t)(mbase + er) * N + nbase]) = v0;
            *reinterpret_cast<float2*>(&C[(size_t)(mbase + er + 8) * N + nbase]) = v1;
        }
    }
}

// ---------------------------------------------------------------------------
// Fused energies + softmax (8q x 128v per block). Also emits bf16 hi/lo
// weights for the tensor-core aligned stage.
// ---------------------------------------------------------------------------
#define QT 8

__global__ __launch_bounds__(256) void energy_softmax_kernel(
    const float* __restrict__ Wh, const float* __restrict__ Uv,
    const float* __restrict__ w,
    float* __restrict__ energies, float* __restrict__ weights,
    __nv_bfloat16* __restrict__ wt_hi, __nv_bfloat16* __restrict__ wt_lo)
{
    __shared__ float As[16][QT];
    __shared__ float Cs[16][132];
    __shared__ float ws[BN];

    const int b = blockIdx.y;
    const int q0 = blockIdx.x * QT;
    const int tid = threadIdx.x;
    const int lane = tid & 31;
    const int ty = tid >> 5;

    const float* Ab = Wh + ((size_t)b * LQ + q0) * BN;
    const float* Cb = Uv + (size_t)b * LV * BN;

    for (int i = tid; i < BN; i += 256) ws[i] = w[i];

    float acc[4] = {0.0f, 0.0f, 0.0f, 0.0f};

    for (int k0 = 0; k0 < BN; k0 += 16) {
        if (tid < 128) {
            const int q = tid >> 4, kk = tid & 15;
            As[kk][q] = Ab[(size_t)q * BN + k0 + kk];
        }
#pragma unroll
        for (int e = 0; e < 8; e++) {
            const int id = tid + e * 256;
            const int v = id >> 4, kk = id & 15;
            Cs[kk][v] = Cb[(size_t)v * BN + k0 + kk];
        }
        __syncthreads();
#pragma unroll
        for (int kk = 0; kk < 16; kk++) {
            const float a = As[kk][ty];
            const float wn = ws[k0 + kk];
#pragma unroll
            for (int j = 0; j < 4; j++) {
                acc[j] += wn * tanh_fast(a + Cs[kk][lane + 32 * j]);
            }
        }
        __syncthreads();
    }

    float mx = fmaxf(fmaxf(acc[0], acc[1]), fmaxf(acc[2], acc[3]));
#pragma unroll
    for (int o = 16; o > 0; o >>= 1) mx = fmaxf(mx, __shfl_xor_sync(0xFFFFFFFFu, mx, o));
    float ex[4], s = 0.0f;
#pragma unroll
    for (int j = 0; j < 4; j++) { ex[j] = __expf(acc[j] - mx); s += ex[j]; }
#pragma unroll
    for (int o = 16; o > 0; o >>= 1) s += __shfl_xor_sync(0xFFFFFFFFu, s, o);
    const float inv = __fdividef(1.0f, s);

    const size_t row = (size_t)b * LQ + q0 + ty;
#pragma unroll
    for (int j = 0; j < 4; j++) {
        const size_t o = row * LV + lane + 32 * j;
        const float wv = ex[j] * inv;
        energies[o] = acc[j];
        weights[o] = wv;
        __nv_bfloat16 h = __float2bfloat16(wv);
        wt_hi[o] = h;
        wt_lo[o] = __float2bfloat16(wv - __bfloat162float(h));
    }
}

// ---------------------------------------------------------------------------
// Tensor-core aligned: out[b,q,QS+f] = sum_v weights[b,q,v] * vis[b,v,f]
// bf16x3 on weights hi/lo (from energy kernel) and pre-split vis hi/lo.
// Block: 64q x 128f, K = 128 (whole). B fragments via ldmatrix.x4.trans.
// Dynamic smem: (64+64+128+128) rows x 136 halves x 2B = 104448 B.
// ---------------------------------------------------------------------------
#define WPITCH 136

__global__ __launch_bounds__(256) void aligned_tc_kernel(
    const __nv_bfloat16* __restrict__ wt_hi, const __nv_bfloat16* __restrict__ wt_lo,
    const __nv_bfloat16* __restrict__ vis_hi, const __nv_bfloat16* __restrict__ vis_lo,
    float* __restrict__ out_sem)
{
    extern __shared__ __nv_bfloat16 asm_[];
    __nv_bfloat16* Wh_s = asm_;
    __nv_bfloat16* Wl_s = asm_ + 64 * WPITCH;
    __nv_bfloat16* Vh_s = asm_ + 128 * WPITCH;
    __nv_bfloat16* Vl_s = asm_ + 256 * WPITCH;

    const int b = blockIdx.y;
    const int f0 = blockIdx.x * 128;
    const int tid = threadIdx.x;
    const int lane = tid & 31;
    const int wid = tid >> 5;
    const int wm = wid >> 2;        // 0..1
    const int wn = wid & 3;         // 0..3
    const int lq = lane >> 3;
    const int lr = lane & 7;

    // stage weights 64x128 hi/lo (1024 chunks each)
#pragma unroll
    for (int e = 0; e < 4; e++) {
        int idx = tid + e * 256;
        int row = idx >> 4, c = (idx & 15) * 8;
        cpasync16(&Wh_s[row * WPITCH + c], &wt_hi[((size_t)b * LQ + row) * LV + c]);
        cpasync16(&Wl_s[row * WPITCH + c], &wt_lo[((size_t)b * LQ + row) * LV + c]);
    }
    // stage vis 128x128 slice hi/lo (2048 chunks each)
#pragma unroll
    for (int e = 0; e < 8; e++) {
        int idx = tid + e * 256;
        int row = idx >> 4, c = (idx & 15) * 8;
        cpasync16(&Vh_s[row * WPITCH + c],
                  &vis_hi[((size_t)b * LV + row) * FS + f0 + c]);
        cpasync16(&Vl_s[row * WPITCH + c],
                  &vis_lo[((size_t)b * LV + row) * FS + f0 + c]);
    }
    asm volatile("cp.async.commit_group;");
    asm volatile("cp.async.wait_group 0;" ::: "memory");
    __syncthreads();

    float acc[2][4][4];
#pragma unroll
    for (int i = 0; i < 2; i++)
#pragma unroll
        for (int j = 0; j < 4; j++)
#pragma unroll
            for (int r = 0; r < 4; r++) acc[i][j][r] = 0.0f;

#pragma unroll
    for (int ks = 0; ks < 8; ks++) {
        uint32_t ah[2][4], al[2][4];
#pragma unroll
        for (int ma = 0; ma < 2; ma++) {
            const int m_local = wm * 32 + ma * 16 + (lq & 1) * 8 + lr;
            const int k_local = ks * 16 + (lq >> 1) * 8;
            ldsm_x4(ah[ma][0], ah[ma][1], ah[ma][2], ah[ma][3],
                    smem_u32(&Wh_s[m_local * WPITCH + k_local]));
            ldsm_x4(al[ma][0], al[ma][1], al[ma][2], al[ma][3],
                    smem_u32(&Wl_s[m_local * WPITCH + k_local]));
        }
        uint32_t bh[4][2], bl[4][2];
#pragma unroll
        for (int np = 0; np < 2; np++) {
            const int krow = ks * 16 + (lq & 1) * 8 + lr;
            const int ncol = wn * 32 + np * 16 + (lq >> 1) * 8;
            uint32_t r0, r1, r2, r3;
            ldsm_x4_t(r0, r1, r2, r3, smem_u32(&Vh_s[krow * WPITCH + ncol]));
            bh[np * 2][0] = r0; bh[np * 2][1] = r1;
            bh[np * 2 + 1][0] = r2; bh[np * 2 + 1][1] = r3;
            ldsm_x4_t(r0, r1, r2, r3, smem_u32(&Vl_s[krow * WPITCH + ncol]));
            bl[np * 2][0] = r0; bl[np * 2][1] = r1;
            bl[np * 2 + 1][0] = r2; bl[np * 2 + 1][1] = r3;
        }
#pragma unroll
        for (int ma = 0; ma < 2; ma++)
#pragma unroll
            for (int na = 0; na < 4; na++) {
                mma_bf16(acc[ma][na], ah[ma], bh[na]);
                mma_bf16(acc[ma][na], ah[ma], bl[na]);
                mma_bf16(acc[ma][na], al[ma], bh[na]);
            }
    }

    const int er = lane >> 2;
    const int ec = (lane & 3) << 1;
#pragma unroll
    for (int ma = 0; ma < 2; ma++) {
        const int qbase = wm * 32 + ma * 16;
#pragma unroll
        for (int na = 0; na < 4; na++) {
            const int f = f0 + wn * 32 + na * 8 + ec;
            float2 v0, v1;
            v0.x = acc[ma][na][0]; v0.y = acc[ma][na][1];
            v1.x = acc[ma][na][2]; v1.y = acc[ma][na][3];
            *reinterpret_cast<float2*>(
                &out_sem[((size_t)b * LQ + qbase + er) * (QS + FS) + QS + f]) = v0;
            *reinterpret_cast<float2*>(
                &out_sem[((size_t)b * LQ + qbase + er + 8) * (QS + FS) + QS + f]) = v1;
        }
    }
}

// Copy phr_feats into concat output columns [0, QS)
__global__ __launch_bounds__(256) void copy_phr_kernel(
    const float* __restrict__ phr, float* __restrict__ out_sem)
{
    const size_t total4 = (size_t)NB * LQ * QS / 4;
    for (size_t i = (size_t)blockIdx.x * blockDim.x + threadIdx.x; i < total4;
         i += (size_t)gridDim.x * blockDim.x) {
        size_t elem = i * 4;
        size_t row = elem >> 9;
        size_t c = elem & 511;
        float4 v = *reinterpret_cast<const float4*>(phr + elem);
        *reinterpret_cast<float4*>(out_sem + row * (QS + FS) + c) = v;
    }
}

extern "C" void kernel_launch(void* const* d_in, const int* in_sizes, int n_in,
                              void* d_out, int out_size)
{
    const float* phr  = (const float*)d_in[0];
    const float* vis  = (const float*)d_in[1];
    const float* W    = (const float*)d_in[2];
    const float* U    = (const float*)d_in[3];
    const float* bias = (const float*)d_in[4];
    const float* w    = (const float*)d_in[5];

    float* out = (float*)d_out;
    float* out_sem = out;
    float* out_w   = out + (size_t)NB * LQ * (QS + FS);
    float* out_e   = out_w + (size_t)NB * LQ * LV;

    float *Wh, *Uv;
    __nv_bfloat16 *phr_hi, *phr_lo, *vis_hi, *vis_lo, *W_hi, *W_lo, *U_hi, *U_lo;
    __nv_bfloat16 *wt_hi, *wt_lo;
    cudaGetSymbolAddress((void**)&Wh, g_Wh);
    cudaGetSymbolAddress((void**)&Uv, g_Uv);
    cudaGetSymbolAddress((void**)&phr_hi, g_phr_hi);
    cudaGetSymbolAddress((void**)&phr_lo, g_phr_lo);
    cudaGetSymbolAddress((void**)&vis_hi, g_vis_hi);
    cudaGetSymbolAddress((void**)&vis_lo, g_vis_lo);
    cudaGetSymbolAddress((void**)&W_hi, g_W_hi);
    cudaGetSymbolAddress((void**)&W_lo, g_W_lo);
    cudaGetSymbolAddress((void**)&U_hi, g_U_hi);
    cudaGetSymbolAddress((void**)&U_lo, g_U_lo);
    cudaGetSymbolAddress((void**)&wt_hi, g_wt_hi);
    cudaGetSymbolAddress((void**)&wt_lo, g_wt_lo);

    cudaFuncSetAttribute(gemm_nt_bf16x3,
                         cudaFuncAttributeMaxDynamicSharedMemorySize, 61440);
    cudaFuncSetAttribute(aligned_tc_kernel,
                         cudaFuncAttributeMaxDynamicSharedMemorySize, 104448);

    // split: phr(262144 f4), vis(1048576 f4), W(65536 f4), U(131072 f4)
    split4_kernel<<<5888, 256>>>(phr, phr_hi, phr_lo, 262144,
                                 vis, vis_hi, vis_lo, 1048576,
                                 W,   W_hi,   W_lo,   65536,
                                 U,   U_hi,   U_lo,   131072);

    // Wh = phr @ W^T + b   (M=2048, N=512, K=512)
    gemm_nt_bf16x3<<<dim3(BN / 64, (NB * LQ) / 128), 256, 61440>>>(
        phr_hi, phr_lo, W_hi, W_lo, bias, Wh, NB * LQ, BN, QS);
    // Uv = vis @ U^T       (M=4096, N=512, K=1024)
    gemm_nt_bf16x3<<<dim3(BN / 64, (NB * LV) / 128), 256, 61440>>>(
        vis_hi, vis_lo, U_hi, U_lo, nullptr, Uv, NB * LV, BN, FS);

    // energies + softmax (+ bf16 weight splits)
    energy_softmax_kernel<<<dim3(LQ / QT, NB), 256>>>(Wh, Uv, w, out_e, out_w,
                                                      wt_hi, wt_lo);
    // aligned via tensor cores
    aligned_tc_kernel<<<dim3(FS / 128, NB), 256, 104448>>>(wt_hi, wt_lo,
                                                           vis_hi, vis_lo,
                                                           out_sem);
    // concat copy
    copy_phr_kernel<<<1024, 256>>>(phr, out_sem);
}